// round 5
// baseline (speedup 1.0000x reference)
#include <cuda_runtime.h>
#include <math.h>

#define BB 128
#define TT 25
#define VOCAB 10000
#define EMBD 512
#define VGGD 4096
#define HIDD 512

// ---------------- scratch (device globals; no allocation allowed) ------------
__device__ float g_h0[BB * HIDD];
__device__ float g_E[TT * BB * EMBD];          // gathered embeddings, row = t*B+b
__device__ float g_X0[TT * BB * 3 * HIDD];     // precomputed layer-0 input proj [u|r|c]
__device__ float g_S1[TT * BB * HIDD];         // s1 per step
__device__ float g_s0buf[2][BB * HIDD];        // s0 double buffer
__device__ float g_gu0[BB * HIDD];
__device__ float g_gr0[BB * HIDD];
__device__ float g_gu1[BB * HIDD];
__device__ float g_gr1[BB * HIDD];
__device__ float g_W0top[HIDD * 3 * HIDD];     // packed [Wu0_top|Wr0_top|Wc0_top]
__device__ float g_b0top[3 * HIDD];

// ---------------- pack layer-0 top weights -----------------------------------
__global__ void pack_w0top(const float* __restrict__ Wu0, const float* __restrict__ Wr0,
                           const float* __restrict__ Wc0, const float* __restrict__ bu0,
                           const float* __restrict__ br0, const float* __restrict__ bc0) {
    int idx = blockIdx.x * blockDim.x + threadIdx.x;
    const int total = HIDD * 3 * HIDD;
    if (idx < total) {
        int k = idx / (3 * HIDD);
        int j = idx - k * (3 * HIDD);
        float v;
        if (j < HIDD)           v = Wu0[k * HIDD + j];
        else if (j < 2 * HIDD)  v = Wr0[k * HIDD + (j - HIDD)];
        else                    v = Wc0[k * HIDD + (j - 2 * HIDD)];
        g_W0top[idx] = v;
    }
    if (idx < 3 * HIDD) {
        g_b0top[idx] = (idx < HIDD) ? bu0[idx]
                     : (idx < 2 * HIDD) ? br0[idx - HIDD]
                                        : bc0[idx - 2 * HIDD];
    }
}

// ---------------- embedding gather -------------------------------------------
__global__ void embed_gather(const float* __restrict__ emb, const int* __restrict__ tokens) {
    int r = blockIdx.x;              // r = t*B + b
    int t = r / BB;
    int b = r - t * BB;
    int tok = tokens[b * TT + t];
    const float4* src = (const float4*)(emb + (size_t)tok * EMBD);
    float4* dst = (float4*)(g_E + (size_t)r * EMBD);
    dst[threadIdx.x] = src[threadIdx.x];   // 128 threads * float4 = 512 floats
}

// ---------------- big tiled SGEMM: C = A@W + bias ----------------------------
// 128x128 tile, BK=8, 256 threads, 8x8 per thread (split 4+4 pattern).
// AREMAP=1: A row = (m%T)*B + m/T  (logits: output rows are b*T+t order)
template <int AREMAP>
__global__ __launch_bounds__(256) void sgemm_big(
    const float* __restrict__ A, const float* __restrict__ W,
    const float* __restrict__ bias, float* __restrict__ C,
    int M, int N, int K)
{
    __shared__ float As[8][128];
    __shared__ float Ws[8][128];
    int tid = threadIdx.x;
    int m0 = blockIdx.y * 128;
    int n0 = blockIdx.x * 128;
    int tx = tid & 15;
    int ty = tid >> 4;

    float acc[8][8];
#pragma unroll
    for (int i = 0; i < 8; i++)
#pragma unroll
        for (int j = 0; j < 8; j++) acc[i][j] = 0.f;

    int lar = tid >> 1;          // A row in tile (0..127)
    int lak = (tid & 1) * 4;     // k sub-offset 0/4
    int arow = m0 + lar;
    if (AREMAP) arow = (arow % TT) * BB + (arow / TT);
    const float* Aptr = A + (size_t)arow * K;
    int lwk = tid >> 5;          // 0..7
    int lwc = (tid & 31) * 4;    // 0..124

    for (int k0 = 0; k0 < K; k0 += 8) {
        float4 av = *(const float4*)(Aptr + k0 + lak);
        As[lak + 0][lar] = av.x;
        As[lak + 1][lar] = av.y;
        As[lak + 2][lar] = av.z;
        As[lak + 3][lar] = av.w;

        int wn = n0 + lwc;
        const float* Wp = W + (size_t)(k0 + lwk) * N + wn;
        float4 wv;
        if (wn + 3 < N) {
            wv = *(const float4*)Wp;
        } else {
            wv.x = (wn + 0 < N) ? Wp[0] : 0.f;
            wv.y = (wn + 1 < N) ? Wp[1] : 0.f;
            wv.z = (wn + 2 < N) ? Wp[2] : 0.f;
            wv.w = (wn + 3 < N) ? Wp[3] : 0.f;
        }
        *(float4*)&Ws[lwk][lwc] = wv;
        __syncthreads();

#pragma unroll
        for (int kk = 0; kk < 8; kk++) {
            float4 a0 = *(const float4*)&As[kk][ty * 4];
            float4 a1 = *(const float4*)&As[kk][64 + ty * 4];
            float4 w0 = *(const float4*)&Ws[kk][tx * 4];
            float4 w1 = *(const float4*)&Ws[kk][64 + tx * 4];
            float ar[8] = {a0.x, a0.y, a0.z, a0.w, a1.x, a1.y, a1.z, a1.w};
            float wr[8] = {w0.x, w0.y, w0.z, w0.w, w1.x, w1.y, w1.z, w1.w};
#pragma unroll
            for (int i = 0; i < 8; i++)
#pragma unroll
                for (int j = 0; j < 8; j++)
                    acc[i][j] += ar[i] * wr[j];
        }
        __syncthreads();
    }

#pragma unroll
    for (int i = 0; i < 8; i++) {
        int row = m0 + ((i < 4) ? (ty * 4 + i) : (64 + ty * 4 + i - 4));
        float* Crow = C + (size_t)row * N;
#pragma unroll
        for (int j = 0; j < 8; j++) {
            int col = n0 + ((j < 4) ? (tx * 4 + j) : (64 + tx * 4 + j - 4));
            if (col < N) Crow[col] = acc[i][j] + bias[col];
        }
    }
}

// ---------------- small GEMM for the recurrence ------------------------------
struct SP {
    const float* A1;
    const float* A2;
    const float* A3;
    const float* W0;
    const float* W1;
    const float* add0;
    const float* add1;
    float* out0;
    float* out1;
    const float* gu;
    const float* hprev;
    int K;
    int lda;
};

// AMODE: 0 plain(A1,lda)  1 concat2(A1|A2)  2 concat_mul(A1 | A2*A3)  3 mul(A1*A2)
template <int AMODE>
__device__ __forceinline__ float fetchA(const SP& p, int m, int k) {
    if (AMODE == 0) return p.A1[(size_t)m * p.lda + k];
    if (AMODE == 1) return (k < HIDD) ? p.A1[m * HIDD + k] : p.A2[m * HIDD + k - HIDD];
    if (AMODE == 2) return (k < HIDD) ? p.A1[m * HIDD + k]
                                      : p.A2[m * HIDD + k - HIDD] * p.A3[m * HIDD + k - HIDD];
    return p.A1[m * HIDD + k] * p.A2[m * HIDD + k];
}

// EP: 0 sigmoid(acc + addX[m*1536+n])   1 sigmoid(acc + bias[n])
//     2 GRU with addX                   3 GRU with bias
//     4 tanh(acc + bias[n])
template <int AMODE, int EP>
__global__ __launch_bounds__(128) void gemm_small(SP p) {
    __shared__ float As[16][16];
    __shared__ float Ws[16][32];
    int tid = threadIdx.x;
    int n0 = blockIdx.x * 32;
    int m0 = blockIdx.y * 16;
    int z = blockIdx.z;
    const float* W   = z ? p.W1   : p.W0;
    const float* add = z ? p.add1 : p.add0;
    float* out       = z ? p.out1 : p.out0;

    int tx = tid & 7;
    int ty = tid >> 3;               // 0..15 (also used as lwk)
    int lwc = tx * 4;

    float acc0 = 0.f, acc1 = 0.f, acc2 = 0.f, acc3 = 0.f;

    for (int k0 = 0; k0 < p.K; k0 += 16) {
        {
            int m = tid >> 4, k = tid & 15;
            As[k][m] = fetchA<AMODE>(p, m0 + m, k0 + k);
            int i1 = tid + 128;
            m = i1 >> 4; k = i1 & 15;
            As[k][m] = fetchA<AMODE>(p, m0 + m, k0 + k);
        }
        *(float4*)&Ws[ty][lwc] = *(const float4*)(W + (size_t)(k0 + ty) * HIDD + n0 + lwc);
        __syncthreads();
#pragma unroll
        for (int kk = 0; kk < 16; kk++) {
            float a = As[kk][ty];
            float4 w = *(const float4*)&Ws[kk][tx * 4];
            acc0 += a * w.x;
            acc1 += a * w.y;
            acc2 += a * w.z;
            acc3 += a * w.w;
        }
        __syncthreads();
    }

    int m = m0 + ty;
    int n = n0 + tx * 4;
    float addv0, addv1, addv2, addv3;
    if (EP == 0 || EP == 2) {        // matrix add, ld = 1536 (X0 layout)
        const float* ap = add + (size_t)m * 1536 + n;
        addv0 = ap[0]; addv1 = ap[1]; addv2 = ap[2]; addv3 = ap[3];
    } else {
        addv0 = add[n]; addv1 = add[n + 1]; addv2 = add[n + 2]; addv3 = add[n + 3];
    }
    float r0 = acc0 + addv0, r1 = acc1 + addv1, r2 = acc2 + addv2, r3 = acc3 + addv3;
    float* op = out + (size_t)m * HIDD + n;
    if (EP == 0 || EP == 1) {
        op[0] = 1.f / (1.f + expf(-r0));
        op[1] = 1.f / (1.f + expf(-r1));
        op[2] = 1.f / (1.f + expf(-r2));
        op[3] = 1.f / (1.f + expf(-r3));
    } else if (EP == 4) {
        op[0] = tanhf(r0);
        op[1] = tanhf(r1);
        op[2] = tanhf(r2);
        op[3] = tanhf(r3);
    } else {                         // GRU combine
        const float* gp = p.gu + (size_t)m * HIDD + n;
        const float* hp = p.hprev + (size_t)m * HIDD + n;
        op[0] = gp[0] * hp[0] + (1.f - gp[0]) * tanhf(r0);
        op[1] = gp[1] * hp[1] + (1.f - gp[1]) * tanhf(r1);
        op[2] = gp[2] * hp[2] + (1.f - gp[2]) * tanhf(r2);
        op[3] = gp[3] * hp[3] + (1.f - gp[3]) * tanhf(r3);
    }
}

// ---------------- final state write ------------------------------------------
__global__ void write_state(float* __restrict__ out) {
    int idx = blockIdx.x * blockDim.x + threadIdx.x;
    if (idx < BB * HIDD) {
        size_t base = (size_t)BB * TT * VOCAB;
        out[base + idx] = g_s0buf[(TT - 1) & 1][idx];                 // s0 final
        out[base + BB * HIDD + idx] = g_S1[(size_t)(TT - 1) * BB * HIDD + idx]; // s1 final
    }
}

// ---------------- host driver -------------------------------------------------
template <typename Sym>
static float* sym(Sym& s) {
    void* p = nullptr;
    cudaGetSymbolAddress(&p, s);
    return (float*)p;
}

extern "C" void kernel_launch(void* const* d_in, const int* in_sizes, int n_in,
                              void* d_out, int out_size) {
    // metadata order (is_train may or may not be serialized as a scalar input)
    const float* vgg     = (const float*)d_in[0];
    const int*   xTokens = (const int*)d_in[1];
    int i = 2;
    if (n_in >= 20 && in_sizes[2] == 1) i = 3;   // skip is_train scalar
    const float* emb   = (const float*)d_in[i++];
    const float* W_in  = (const float*)d_in[i++];
    const float* b_in  = (const float*)d_in[i++];
    const float* Wu0   = (const float*)d_in[i++];
    const float* bu0   = (const float*)d_in[i++];
    const float* Wr0   = (const float*)d_in[i++];
    const float* br0   = (const float*)d_in[i++];
    const float* Wc0   = (const float*)d_in[i++];
    const float* bc0   = (const float*)d_in[i++];
    const float* Wu1   = (const float*)d_in[i++];
    const float* bu1   = (const float*)d_in[i++];
    const float* Wr1   = (const float*)d_in[i++];
    const float* br1   = (const float*)d_in[i++];
    const float* Wc1   = (const float*)d_in[i++];
    const float* bc1   = (const float*)d_in[i++];
    const float* W_out = (const float*)d_in[i++];
    const float* b_out = (const float*)d_in[i++];
    float* out = (float*)d_out;

    float* pE     = sym(g_E);
    float* pX0    = sym(g_X0);
    float* pS1    = sym(g_S1);
    float* pH0    = sym(g_h0);
    float* pW0top = sym(g_W0top);
    float* pB0top = sym(g_b0top);
    float* pGu0   = sym(g_gu0);
    float* pGr0   = sym(g_gr0);
    float* pGu1   = sym(g_gu1);
    float* pGr1   = sym(g_gr1);
    float* pS0b   = sym(g_s0buf);   // [2][B*HID] contiguous

    // 1) pack layer-0 top weights + biases
    pack_w0top<<<(HIDD * 3 * HIDD + 255) / 256, 256>>>(Wu0, Wr0, Wc0, bu0, br0, bc0);

    // 2) embedding gather
    embed_gather<<<TT * BB, 128>>>(emb, xTokens);

    // 3) h0 = tanh(vgg @ W_in + b_in)
    {
        SP p = {};
        p.A1 = vgg; p.lda = VGGD; p.K = VGGD;
        p.W0 = W_in; p.add0 = b_in; p.out0 = pH0;
        gemm_small<0, 4><<<dim3(HIDD / 32, BB / 16, 1), 128>>>(p);
    }

    // 4) X0 = E_all @ W0top + b0top   [3200,512]@[512,1536]
    sgemm_big<0><<<dim3(3 * HIDD / 128, TT * BB / 128), 256>>>(
        pE, pW0top, pB0top, pX0, TT * BB, 3 * HIDD, HIDD);

    // 5) recurrence
    for (int t = 0; t < TT; t++) {
        const float* s0prev = (t == 0) ? pH0 : (pS0b + (size_t)((t - 1) & 1) * BB * HIDD);
        float*       s0cur  = pS0b + (size_t)(t & 1) * BB * HIDD;
        const float* s1prev = (t == 0) ? pH0 : (pS1 + (size_t)(t - 1) * BB * HIDD);
        float*       s1cur  = pS1 + (size_t)t * BB * HIDD;
        const float* X0t    = pX0 + (size_t)t * BB * 3 * HIDD;

        // layer 0 gates u,r: sigmoid(X0[u|r] + s0 @ W_bot)
        {
            SP p = {};
            p.A1 = s0prev; p.lda = HIDD; p.K = HIDD;
            p.W0 = Wu0 + HIDD * HIDD; p.W1 = Wr0 + HIDD * HIDD;
            p.add0 = X0t; p.add1 = X0t + HIDD;
            p.out0 = pGu0; p.out1 = pGr0;
            gemm_small<0, 0><<<dim3(HIDD / 32, BB / 16, 2), 128>>>(p);
        }
        // layer 0 candidate + combine -> s0cur
        {
            SP p = {};
            p.A1 = pGr0; p.A2 = s0prev; p.K = HIDD;
            p.W0 = Wc0 + HIDD * HIDD;
            p.add0 = X0t + 2 * HIDD;
            p.gu = pGu0; p.hprev = s0prev; p.out0 = s0cur;
            gemm_small<3, 2><<<dim3(HIDD / 32, BB / 16, 1), 128>>>(p);
        }
        // layer 1 gates u,r: sigmoid([s0cur|s1prev] @ W + b)
        {
            SP p = {};
            p.A1 = s0cur; p.A2 = s1prev; p.K = 2 * HIDD;
            p.W0 = Wu1; p.W1 = Wr1;
            p.add0 = bu1; p.add1 = br1;
            p.out0 = pGu1; p.out1 = pGr1;
            gemm_small<1, 1><<<dim3(HIDD / 32, BB / 16, 2), 128>>>(p);
        }
        // layer 1 candidate + combine -> s1cur (stored in history for logits GEMM)
        {
            SP p = {};
            p.A1 = s0cur; p.A2 = pGr1; p.A3 = s1prev; p.K = 2 * HIDD;
            p.W0 = Wc1; p.add0 = bc1;
            p.gu = pGu1; p.hprev = s1prev; p.out0 = s1cur;
            gemm_small<2, 3><<<dim3(HIDD / 32, BB / 16, 1), 128>>>(p);
        }
    }

    // 6) logits = S1 @ W_out + b_out, output rows in (b*T+t) order via A-remap
    sgemm_big<1><<<dim3((VOCAB + 127) / 128, TT * BB / 128), 256>>>(
        pS1, W_out, b_out, out, TT * BB, VOCAB, HIDD);

    // 7) final state [2, B, HID]
    write_state<<<(BB * HIDD + 255) / 256, 256>>>(out);
}

// round 6
// speedup vs baseline: 1.4290x; 1.4290x over previous
#include <cuda_runtime.h>
#include <math.h>

#define BB 128
#define TT 25
#define VOCAB 10000
#define EMBD 512
#define VGGD 4096
#define HIDD 512
#define GBLK 128
#define BK 32

// ---------------- scratch (device globals; no allocation allowed) ------------
__device__ float g_h0[BB * HIDD];
__device__ float g_E[TT * BB * EMBD];          // gathered embeddings, row = t*B+b
__device__ float g_X0[TT * BB * 3 * HIDD];     // precomputed layer-0 input proj [u|r|c]
__device__ float g_S1[TT * BB * HIDD];         // s1 per step
__device__ float g_s0buf[2][BB * HIDD];        // s0 double buffer
__device__ float g_gu0[BB * HIDD];
__device__ float g_gr0[BB * HIDD];
__device__ float g_gu1[BB * HIDD];
__device__ float g_gr1[BB * HIDD];
__device__ float g_W0top[HIDD * 3 * HIDD];     // packed [Wu0_top|Wr0_top|Wc0_top]
__device__ float g_b0top[3 * HIDD];
__device__ unsigned g_bar_count;               // zero-init; returns to 0 each launch
__device__ unsigned g_bar_sense;               // toggles; read at kernel start

// ---------------- pack layer-0 top weights -----------------------------------
__global__ void pack_w0top(const float* __restrict__ Wu0, const float* __restrict__ Wr0,
                           const float* __restrict__ Wc0, const float* __restrict__ bu0,
                           const float* __restrict__ br0, const float* __restrict__ bc0) {
    int idx = blockIdx.x * blockDim.x + threadIdx.x;
    const int total = HIDD * 3 * HIDD;
    if (idx < total) {
        int k = idx / (3 * HIDD);
        int j = idx - k * (3 * HIDD);
        float v;
        if (j < HIDD)           v = Wu0[k * HIDD + j];
        else if (j < 2 * HIDD)  v = Wr0[k * HIDD + (j - HIDD)];
        else                    v = Wc0[k * HIDD + (j - 2 * HIDD)];
        g_W0top[idx] = v;
    }
    if (idx < 3 * HIDD) {
        g_b0top[idx] = (idx < HIDD) ? bu0[idx]
                     : (idx < 2 * HIDD) ? br0[idx - HIDD]
                                        : bc0[idx - 2 * HIDD];
    }
}

// ---------------- embedding gather -------------------------------------------
__global__ void embed_gather(const float* __restrict__ emb, const int* __restrict__ tokens) {
    int r = blockIdx.x;              // r = t*B + b
    int t = r / BB;
    int b = r - t * BB;
    int tok = tokens[b * TT + t];
    const float4* src = (const float4*)(emb + (size_t)tok * EMBD);
    float4* dst = (float4*)(g_E + (size_t)r * EMBD);
    dst[threadIdx.x] = src[threadIdx.x];   // 128 threads * float4 = 512 floats
}

// ---------------- big tiled SGEMM: C = A@W + bias ----------------------------
template <int AREMAP>
__global__ __launch_bounds__(256) void sgemm_big(
    const float* __restrict__ A, const float* __restrict__ W,
    const float* __restrict__ bias, float* __restrict__ C,
    int M, int N, int K)
{
    __shared__ float As[8][128];
    __shared__ float Ws[8][128];
    int tid = threadIdx.x;
    int m0 = blockIdx.y * 128;
    int n0 = blockIdx.x * 128;
    int tx = tid & 15;
    int ty = tid >> 4;

    float acc[8][8];
#pragma unroll
    for (int i = 0; i < 8; i++)
#pragma unroll
        for (int j = 0; j < 8; j++) acc[i][j] = 0.f;

    int lar = tid >> 1;
    int lak = (tid & 1) * 4;
    int arow = m0 + lar;
    if (AREMAP) arow = (arow % TT) * BB + (arow / TT);
    const float* Aptr = A + (size_t)arow * K;
    int lwk = tid >> 5;
    int lwc = (tid & 31) * 4;

    for (int k0 = 0; k0 < K; k0 += 8) {
        float4 av = *(const float4*)(Aptr + k0 + lak);
        As[lak + 0][lar] = av.x;
        As[lak + 1][lar] = av.y;
        As[lak + 2][lar] = av.z;
        As[lak + 3][lar] = av.w;

        int wn = n0 + lwc;
        const float* Wp = W + (size_t)(k0 + lwk) * N + wn;
        float4 wv;
        if (wn + 3 < N) {
            wv = *(const float4*)Wp;
        } else {
            wv.x = (wn + 0 < N) ? Wp[0] : 0.f;
            wv.y = (wn + 1 < N) ? Wp[1] : 0.f;
            wv.z = (wn + 2 < N) ? Wp[2] : 0.f;
            wv.w = (wn + 3 < N) ? Wp[3] : 0.f;
        }
        *(float4*)&Ws[lwk][lwc] = wv;
        __syncthreads();

#pragma unroll
        for (int kk = 0; kk < 8; kk++) {
            float4 a0 = *(const float4*)&As[kk][ty * 4];
            float4 a1 = *(const float4*)&As[kk][64 + ty * 4];
            float4 w0 = *(const float4*)&Ws[kk][tx * 4];
            float4 w1 = *(const float4*)&Ws[kk][64 + tx * 4];
            float ar[8] = {a0.x, a0.y, a0.z, a0.w, a1.x, a1.y, a1.z, a1.w};
            float wr[8] = {w0.x, w0.y, w0.z, w0.w, w1.x, w1.y, w1.z, w1.w};
#pragma unroll
            for (int i = 0; i < 8; i++)
#pragma unroll
                for (int j = 0; j < 8; j++)
                    acc[i][j] += ar[i] * wr[j];
        }
        __syncthreads();
    }

#pragma unroll
    for (int i = 0; i < 8; i++) {
        int row = m0 + ((i < 4) ? (ty * 4 + i) : (64 + ty * 4 + i - 4));
        float* Crow = C + (size_t)row * N;
#pragma unroll
        for (int j = 0; j < 8; j++) {
            int col = n0 + ((j < 4) ? (tx * 4 + j) : (64 + tx * 4 + j - 4));
            if (col < N) Crow[col] = acc[i][j] + bias[col];
        }
    }
}

// ================== persistent recurrence kernel =============================
struct RP {
    const float* vgg;
    const float* W_in; const float* b_in;
    const float* Wu0; const float* Wr0; const float* Wc0;
    const float* Wu1; const float* Wr1; const float* Wc1;
    const float* bu1; const float* br1; const float* bc1;
};

// software grid barrier: all 128 blocks co-resident (grid <= 148 SMs)
__device__ __forceinline__ void gridbar(int tid, unsigned* ps) {
    __threadfence();               // make this thread's global writes visible (gpu scope)
    __syncthreads();
    if (tid == 0) {
        unsigned ns = *ps ^ 1u;
        *ps = ns;
        if (atomicAdd(&g_bar_count, 1u) == GBLK - 1) {
            *(volatile unsigned*)&g_bar_count = 0;
            __threadfence();
            *(volatile unsigned*)&g_bar_sense = ns;
        } else {
            while (*(volatile unsigned*)&g_bar_sense != ns) { __nanosleep(32); }
        }
        __threadfence();
    }
    __syncthreads();
}

// AMODE: 0 plain(A1,lda)  1 concat2(A1|A2)  2 concat_mul(A1 | A2*A3)  3 mul(A1*A2)
// all dynamic operands via __ldcg (L2-coherent reads within the persistent kernel)
template <int AMODE>
__device__ __forceinline__ float2 fetchA2(const float* A1, const float* A2,
                                          const float* A3, int lda, int m, int k) {
    if (AMODE == 0) return __ldcg((const float2*)(A1 + (size_t)m * lda + k));
    if (AMODE == 1) {
        const float* p = (k < HIDD) ? (A1 + m * HIDD + k) : (A2 + m * HIDD + k - HIDD);
        return __ldcg((const float2*)p);
    }
    if (AMODE == 2) {
        if (k < HIDD) return __ldcg((const float2*)(A1 + m * HIDD + k));
        float2 a = __ldcg((const float2*)(A2 + m * HIDD + k - HIDD));
        float2 b = __ldcg((const float2*)(A3 + m * HIDD + k - HIDD));
        return make_float2(a.x * b.x, a.y * b.y);
    }
    {
        float2 a = __ldcg((const float2*)(A1 + m * HIDD + k));
        float2 b = __ldcg((const float2*)(A2 + m * HIDD + k));
        return make_float2(a.x * b.x, a.y * b.y);
    }
}

// One block computes a [16 x (CPT*16)] output tile. 256 threads, 1 row x CPT cols each.
// W is row-major [K x 512]; wcol0 = column offset. Software-pipelined BK=32 chunks.
template <int CPT, int AMODE>
__device__ __forceinline__ void tile_mm(
    float (&acc)[CPT], int m0, const float* __restrict__ W, int wcol0,
    const float* A1, const float* A2, const float* A3, int lda, int K,
    float (*As)[36], float (*Ws)[64], int tid)
{
    int tx = tid & 15, ty = tid >> 4;
    int fm = tid >> 4;            // A fill: row 0..15
    int fk = (tid & 15) * 2;      // A fill: k 0,2,..,30

    float2 a_r;
    float4 w_r0, w_r1;

    // W fill mapping
    int wk0, wc0, wk1 = 0, wc1 = 0;
    if (CPT == 4) { wk0 = tid >> 4; wc0 = (tid & 15) * 4; int i1 = tid + 256; wk1 = i1 >> 4; wc1 = (i1 & 15) * 4; }
    else          { wk0 = tid >> 3; wc0 = (tid & 7) * 4; }

    // prologue loads
    a_r = fetchA2<AMODE>(A1, A2, A3, lda, m0 + fm, fk);
    w_r0 = *(const float4*)(W + (size_t)wk0 * HIDD + wcol0 + wc0);
    if (CPT == 4) w_r1 = *(const float4*)(W + (size_t)wk1 * HIDD + wcol0 + wc1);

    for (int k0 = 0; k0 < K; k0 += BK) {
        *(float2*)&As[fm][fk] = a_r;
        *(float4*)&Ws[wk0][wc0] = w_r0;
        if (CPT == 4) *(float4*)&Ws[wk1][wc1] = w_r1;
        __syncthreads();

        int kn = k0 + BK;
        if (kn < K) {
            a_r = fetchA2<AMODE>(A1, A2, A3, lda, m0 + fm, kn + fk);
            w_r0 = *(const float4*)(W + (size_t)(kn + wk0) * HIDD + wcol0 + wc0);
            if (CPT == 4) w_r1 = *(const float4*)(W + (size_t)(kn + wk1) * HIDD + wcol0 + wc1);
        }

#pragma unroll
        for (int kk = 0; kk < BK; kk += 4) {
            float4 av = *(const float4*)&As[ty][kk];
            if (CPT == 4) {
                float4 w;
                w = *(const float4*)&Ws[kk + 0][tx * 4];
                acc[0] += av.x * w.x; acc[1] += av.x * w.y; acc[2] += av.x * w.z; acc[3] += av.x * w.w;
                w = *(const float4*)&Ws[kk + 1][tx * 4];
                acc[0] += av.y * w.x; acc[1] += av.y * w.y; acc[2] += av.y * w.z; acc[3] += av.y * w.w;
                w = *(const float4*)&Ws[kk + 2][tx * 4];
                acc[0] += av.z * w.x; acc[1] += av.z * w.y; acc[2] += av.z * w.z; acc[3] += av.z * w.w;
                w = *(const float4*)&Ws[kk + 3][tx * 4];
                acc[0] += av.w * w.x; acc[1] += av.w * w.y; acc[2] += av.w * w.z; acc[3] += av.w * w.w;
            } else {
                float2 w;
                w = *(const float2*)&Ws[kk + 0][tx * 2];
                acc[0] += av.x * w.x; acc[1] += av.x * w.y;
                w = *(const float2*)&Ws[kk + 1][tx * 2];
                acc[0] += av.y * w.x; acc[1] += av.y * w.y;
                w = *(const float2*)&Ws[kk + 2][tx * 2];
                acc[0] += av.z * w.x; acc[1] += av.z * w.y;
                w = *(const float2*)&Ws[kk + 3][tx * 2];
                acc[0] += av.w * w.x; acc[1] += av.w * w.y;
            }
        }
        __syncthreads();
    }
}

__device__ __forceinline__ float sigm(float x) { return 1.f / (1.f + expf(-x)); }

__global__ __launch_bounds__(256, 1) void recur_kernel(RP p) {
    __shared__ float As[BK > 16 ? 16 : 16][36];   // [16][36]
    __shared__ float Ws[BK][64];
    __shared__ unsigned s_sense;
    int tid = threadIdx.x, bid = blockIdx.x;
    if (tid == 0) s_sense = *(volatile unsigned*)&g_bar_sense;
    int tx = tid & 15, ty = tid >> 4;

    // ---- phase 0: h0 = tanh(vgg @ W_in + b_in), [128x512], K=4096 ----
    {
        int m0 = (bid >> 4) * 16, n0 = (bid & 15) * 32;
        float acc[2] = {0.f, 0.f};
        tile_mm<2, 0>(acc, m0, p.W_in, n0, p.vgg, nullptr, nullptr, VGGD, VGGD, As, Ws, tid);
        int m = m0 + ty;
#pragma unroll
        for (int j = 0; j < 2; j++) {
            int n = n0 + tx * 2 + j;
            g_h0[m * HIDD + n] = tanhf(acc[j] + p.b_in[n]);
        }
    }
    gridbar(tid, &s_sense);

#pragma unroll 1
    for (int t = 0; t < TT; t++) {
        const float* s0prev = (t == 0) ? g_h0 : g_s0buf[(t - 1) & 1];
        float*       s0cur  = g_s0buf[t & 1];
        const float* s1prev = (t == 0) ? g_h0 : (g_S1 + (size_t)(t - 1) * BB * HIDD);
        float*       s1cur  = g_S1 + (size_t)t * BB * HIDD;
        const float* X0t    = g_X0 + (size_t)t * BB * 3 * HIDD;

        // ---- P1: gu0|gr0 = sigmoid(X0[u|r] + s0prev @ W*0_bot), N=1024, K=512 ----
        {
            int m0 = (bid >> 4) * 16;
            int gc0 = (bid & 15) * 64;
            int half = gc0 >= HIDD;
            const float* W = (half ? p.Wr0 : p.Wu0) + HIDD * HIDD;  // bottom half rows
            int wcol0 = gc0 - half * HIDD;
            float acc[4] = {0.f, 0.f, 0.f, 0.f};
            tile_mm<4, 0>(acc, m0, W, wcol0, s0prev, nullptr, nullptr, HIDD, HIDD, As, Ws, tid);
            float* out = half ? g_gr0 : g_gu0;
            int m = m0 + ty;
#pragma unroll
            for (int j = 0; j < 4; j++) {
                int gc = gc0 + tx * 4 + j;
                float v = acc[j] + X0t[m * 3 * HIDD + gc];
                out[m * HIDD + (gc & (HIDD - 1))] = sigm(v);
            }
        }
        gridbar(tid, &s_sense);

        // ---- P2: s0cur = gu0*s0prev + (1-gu0)*tanh(X0[c] + (gr0*s0prev)@Wc0_bot), K=512 ----
        {
            int m0 = (bid >> 4) * 16, n0 = (bid & 15) * 32;
            float acc[2] = {0.f, 0.f};
            tile_mm<2, 3>(acc, m0, p.Wc0 + HIDD * HIDD, n0, g_gr0, s0prev, nullptr,
                          HIDD, HIDD, As, Ws, tid);
            int m = m0 + ty;
#pragma unroll
            for (int j = 0; j < 2; j++) {
                int n = n0 + tx * 2 + j;
                float c  = tanhf(acc[j] + X0t[m * 3 * HIDD + 2 * HIDD + n]);
                float gu = __ldcg(g_gu0 + m * HIDD + n);
                float h  = __ldcg(s0prev + m * HIDD + n);
                s0cur[m * HIDD + n] = gu * h + (1.f - gu) * c;
            }
        }
        gridbar(tid, &s_sense);

        // ---- P3: gu1|gr1 = sigmoid([s0cur|s1prev] @ W*1 + b), N=1024, K=1024 ----
        {
            int m0 = (bid >> 4) * 16;
            int gc0 = (bid & 15) * 64;
            int half = gc0 >= HIDD;
            const float* W = half ? p.Wr1 : p.Wu1;
            const float* b = half ? p.br1 : p.bu1;
            int wcol0 = gc0 - half * HIDD;
            float acc[4] = {0.f, 0.f, 0.f, 0.f};
            tile_mm<4, 1>(acc, m0, W, wcol0, s0cur, s1prev, nullptr, HIDD, 2 * HIDD, As, Ws, tid);
            float* out = half ? g_gr1 : g_gu1;
            int m = m0 + ty;
#pragma unroll
            for (int j = 0; j < 4; j++) {
                int gc = gc0 + tx * 4 + j;
                int n = gc & (HIDD - 1);
                out[m * HIDD + n] = sigm(acc[j] + b[n]);
            }
        }
        gridbar(tid, &s_sense);

        // ---- P4: s1cur = gu1*s1prev + (1-gu1)*tanh([s0cur|gr1*s1prev]@Wc1 + bc1), K=1024 ----
        {
            int m0 = (bid >> 4) * 16, n0 = (bid & 15) * 32;
            float acc[2] = {0.f, 0.f};
            tile_mm<2, 2>(acc, m0, p.Wc1, n0, s0cur, g_gr1, s1prev, HIDD, 2 * HIDD, As, Ws, tid);
            int m = m0 + ty;
#pragma unroll
            for (int j = 0; j < 2; j++) {
                int n = n0 + tx * 2 + j;
                float c  = tanhf(acc[j] + p.bc1[n]);
                float gu = __ldcg(g_gu1 + m * HIDD + n);
                float h  = __ldcg(s1prev + m * HIDD + n);
                s1cur[m * HIDD + n] = gu * h + (1.f - gu) * c;
            }
        }
        gridbar(tid, &s_sense);
    }
}

// ---------------- final state write ------------------------------------------
__global__ void write_state(float* __restrict__ out) {
    int idx = blockIdx.x * blockDim.x + threadIdx.x;
    if (idx < BB * HIDD) {
        size_t base = (size_t)BB * TT * VOCAB;
        out[base + idx] = g_s0buf[(TT - 1) & 1][idx];
        out[base + BB * HIDD + idx] = g_S1[(size_t)(TT - 1) * BB * HIDD + idx];
    }
}

// ---------------- host driver -------------------------------------------------
template <typename Sym>
static float* sym(Sym& s) {
    void* p = nullptr;
    cudaGetSymbolAddress(&p, s);
    return (float*)p;
}

extern "C" void kernel_launch(void* const* d_in, const int* in_sizes, int n_in,
                              void* d_out, int out_size) {
    const float* vgg     = (const float*)d_in[0];
    const int*   xTokens = (const int*)d_in[1];
    int i = 2;
    if (n_in >= 20 && in_sizes[2] == 1) i = 3;   // skip is_train scalar
    const float* emb   = (const float*)d_in[i++];
    const float* W_in  = (const float*)d_in[i++];
    const float* b_in  = (const float*)d_in[i++];
    const float* Wu0   = (const float*)d_in[i++];
    const float* bu0   = (const float*)d_in[i++];
    const float* Wr0   = (const float*)d_in[i++];
    const float* br0   = (const float*)d_in[i++];
    const float* Wc0   = (const float*)d_in[i++];
    const float* bc0   = (const float*)d_in[i++];
    const float* Wu1   = (const float*)d_in[i++];
    const float* bu1   = (const float*)d_in[i++];
    const float* Wr1   = (const float*)d_in[i++];
    const float* br1   = (const float*)d_in[i++];
    const float* Wc1   = (const float*)d_in[i++];
    const float* bc1   = (const float*)d_in[i++];
    const float* W_out = (const float*)d_in[i++];
    const float* b_out = (const float*)d_in[i++];
    float* out = (float*)d_out;

    float* pE     = sym(g_E);
    float* pX0    = sym(g_X0);
    float* pS1    = sym(g_S1);
    float* pW0top = sym(g_W0top);
    float* pB0top = sym(g_b0top);

    // 1) pack layer-0 top weights + biases
    pack_w0top<<<(HIDD * 3 * HIDD + 255) / 256, 256>>>(Wu0, Wr0, Wc0, bu0, br0, bc0);

    // 2) embedding gather
    embed_gather<<<TT * BB, 128>>>(emb, xTokens);

    // 3) X0 = E_all @ W0top + b0top   [3200,512]@[512,1536]
    sgemm_big<0><<<dim3(3 * HIDD / 128, TT * BB / 128), 256>>>(
        pE, pW0top, pB0top, pX0, TT * BB, 3 * HIDD, HIDD);

    // 4) persistent recurrence (h0 + 25 GRU steps, software grid barriers)
    {
        RP rp;
        rp.vgg = vgg; rp.W_in = W_in; rp.b_in = b_in;
        rp.Wu0 = Wu0; rp.Wr0 = Wr0; rp.Wc0 = Wc0;
        rp.Wu1 = Wu1; rp.Wr1 = Wr1; rp.Wc1 = Wc1;
        rp.bu1 = bu1; rp.br1 = br1; rp.bc1 = bc1;
        recur_kernel<<<GBLK, 256>>>(rp);
    }

    // 5) logits = S1 @ W_out + b_out, output rows in (b*T+t) order via A-remap
    sgemm_big<1><<<dim3((VOCAB + 127) / 128, TT * BB / 128), 256>>>(
        pS1, W_out, b_out, out, TT * BB, VOCAB, HIDD);

    // 6) final state [2, B, HID]
    write_state<<<(BB * HIDD + 255) / 256, 256>>>(out);
}